// round 1
// baseline (speedup 1.0000x reference)
#include <cuda_runtime.h>

// Problem constants (from reference)
#define NL        32
#define NFORCING  720
#define NSUB      60
#define DT_STEP   60.0f

// One warp. Lane l owns layer l's (U, V). Neighbor coupling via shuffles.
// Mirrors the reference arithmetic ordering:
//   dU_top[0]  = Kin[0]*TAxnow
//   dU_top[l]  = -Kin[l]*(U[l]-U[l-1])
//   d_U        = f*V + dU_top - Kout*(U - Unext)       (Unext[31]=0)
//   U         += DT*d_U   (simultaneous with V update)
__global__ void __launch_bounds__(32, 1)
junsteak_sim_kernel(const float* __restrict__ pk,
                    const float* __restrict__ TAx,
                    const float* __restrict__ TAy,
                    const float* __restrict__ fc,
                    float* __restrict__ out)
{
    const int lane = threadIdx.x;              // 0..31 == layer index
    const unsigned FULL = 0xffffffffu;

    const float kin  = expf(pk[2 * lane]);
    const float kout = expf(pk[2 * lane + 1]);
    const float f    = fc[0];

    float u = 0.0f, v = 0.0f;

    // Row 0 of both U and V is zeros (initial state); reference never
    // overwrites it (the final .at[720].set is dropped as OOB in JAX).
    out[lane]                  = 0.0f;                 // U[0][lane]
    out[NFORCING * NL + lane]  = 0.0f;                 // V[0][lane]

    const float inv_nsub = 1.0f / (float)NSUB;
    const bool  is_top   = (lane == 0);
    const bool  is_bot   = (lane == NL - 1);

    // Outer forcing steps: reference's write for iout=719 lands at row 720
    // (dropped), so only iterate iout = 0..718 and write rows 1..719.
    for (int iout = 0; iout < NFORCING - 1; ++iout) {
        const float tax0 = TAx[iout];
        const float tax1 = TAx[iout + 1];   // iout+1 <= 719, never clamps
        const float tay0 = TAy[iout];
        const float tay1 = TAy[iout + 1];

        #pragma unroll 10
        for (int iin = 0; iin < NSUB; ++iin) {
            const float aa     = (float)iin * inv_nsub;
            const float taxnow = (1.0f - aa) * tax0 + aa * tax1;
            const float taynow = (1.0f - aa) * tay0 + aa * tay1;

            // Neighbor exchange (independent shuffles, 26-cyc lat each)
            float uprev = __shfl_up_sync  (FULL, u, 1);
            float vprev = __shfl_up_sync  (FULL, v, 1);
            float unext = __shfl_down_sync(FULL, u, 1);
            float vnext = __shfl_down_sync(FULL, v, 1);
            if (is_bot) { unext = 0.0f; vnext = 0.0f; }

            const float dU_top = is_top ?  kin * taxnow
                                        : -kin * (u - uprev);
            const float dV_top = is_top ?  kin * taynow
                                        : -kin * (v - vprev);

            // d_U / d_V from OLD (u, v) — simultaneous update
            const float du =  f * v + dU_top - kout * (u - unext);
            const float dv = -f * u + dV_top - kout * (v - vnext);

            u = fmaf(DT_STEP, du, u);
            v = fmaf(DT_STEP, dv, v);
        }

        out[(iout + 1) * NL + lane]                 = u;   // U[iout+1]
        out[NFORCING * NL + (iout + 1) * NL + lane] = v;   // V[iout+1]
    }
}

extern "C" void kernel_launch(void* const* d_in, const int* in_sizes, int n_in,
                              void* d_out, int out_size)
{
    const float* pk  = (const float*)d_in[0];   // (64,)
    const float* TAx = (const float*)d_in[1];   // (720,)
    const float* TAy = (const float*)d_in[2];   // (720,)
    const float* fc  = (const float*)d_in[3];   // (1,)
    float* out = (float*)d_out;                 // U[720,32] then V[720,32]

    junsteak_sim_kernel<<<1, 32>>>(pk, TAx, TAy, fc, out);
}

// round 2
// speedup vs baseline: 6.6182x; 6.6182x over previous
#include <cuda_runtime.h>

#define NL     32
#define NF     720
#define NSUB   60
#define DTF    60.0f

// Persistent scratch (allocation-free rule: __device__ globals)
__device__ float2 g_P [NL * NL];   // P[row][col], row-major (P = M^60)
__device__ float2 g_g0[NL];        // forcing response vectors
__device__ float2 g_g1[NL];

// ---------------------------------------------------------------------------
// Kernel 1: setup. One block, 32 warps.
//   warp c : propagates column c of M^60 via 60 tridiagonal substeps (shfl).
//   warp 0 : afterwards runs the 60-step injected recurrence for g0, g1.
// ---------------------------------------------------------------------------
__global__ void __launch_bounds__(1024, 1)
setup_kernel(const float* __restrict__ pk, const float* __restrict__ fc)
{
    const unsigned FULL = 0xffffffffu;
    const int lane = threadIdx.x & 31;
    const int warp = threadIdx.x >> 5;

    const float kin  = expf(pk[2 * lane]);
    const float kout = expf(pk[2 * lane + 1]);
    const float dtf  = DTF * fc[0];

    const float ca  = (lane > 0)      ? DTF * kin  : 0.0f;   // sub-diagonal
    const float cb  = (lane < NL - 1) ? DTF * kout : 0.0f;   // super-diagonal
    const float cmr = 1.0f - DTF * (((lane > 0) ? kin : 0.0f) + kout);
    // complex diagonal = cmr - i*dtf

    // ---- column c = warp of P = M^60 ----
    float xr = (lane == warp) ? 1.0f : 0.0f;
    float xi = 0.0f;
    #pragma unroll 4
    for (int s = 0; s < NSUB; ++s) {
        float xr_up = __shfl_up_sync  (FULL, xr, 1);
        float xi_up = __shfl_up_sync  (FULL, xi, 1);
        float xr_dn = __shfl_down_sync(FULL, xr, 1);
        float xi_dn = __shfl_down_sync(FULL, xi, 1);
        float yr = cmr * xr + dtf * xi + ca * xr_up + cb * xr_dn;
        float yi = cmr * xi - dtf * xr + ca * xi_up + cb * xi_dn;
        xr = yr; xi = yi;
    }
    g_P[lane * NL + warp] = make_float2(xr, xi);

    // ---- g0, g1 (warp 0 only) ----
    if (warp == 0) {
        const float scale = DTF * expf(pk[0]);     // DT * Kin[0]
        float y0r = 0.f, y0i = 0.f, y1r = 0.f, y1i = 0.f;
        for (int j = 0; j < NSUB; ++j) {
            float a0r = __shfl_up_sync  (FULL, y0r, 1);
            float a0i = __shfl_up_sync  (FULL, y0i, 1);
            float a1r = __shfl_up_sync  (FULL, y1r, 1);
            float a1i = __shfl_up_sync  (FULL, y1i, 1);
            float b0r = __shfl_down_sync(FULL, y0r, 1);
            float b0i = __shfl_down_sync(FULL, y0i, 1);
            float b1r = __shfl_down_sync(FULL, y1r, 1);
            float b1i = __shfl_down_sync(FULL, y1i, 1);

            float n0r = cmr * y0r + dtf * y0i + ca * a0r + cb * b0r;
            float n0i = cmr * y0i - dtf * y0r + ca * a0i + cb * b0i;
            float n1r = cmr * y1r + dtf * y1i + ca * a1r + cb * b1r;
            float n1i = cmr * y1i - dtf * y1r + ca * a1i + cb * b1i;

            const float aa = (float)j / (float)NSUB;
            if (lane == 0) {
                n0r += scale * (1.0f - aa);   // coefficient of tau_k
                n1r += scale * aa;            // coefficient of tau_{k+1}
            }
            y0r = n0r; y0i = n0i; y1r = n1r; y1i = n1i;
        }
        g_g0[lane] = make_float2(y0r, y0i);
        g_g1[lane] = make_float2(y1r, y1i);
    }
}

// ---------------------------------------------------------------------------
// Kernel 2: serial outer recurrence, one warp.
//   w_{k+1} = P w_k + tau_k g0 + tau_{k+1} g1  ;  U[k]=Re w_k, V[k]=Im w_k
// ---------------------------------------------------------------------------
__global__ void __launch_bounds__(32, 1)
run_kernel(const float* __restrict__ TAx, const float* __restrict__ TAy,
           float* __restrict__ out)
{
    const unsigned FULL = 0xffffffffu;
    const int lane = threadIdx.x;

    // my row of P (64 registers)
    float2 Prow[NL];
    #pragma unroll
    for (int j = 0; j < NL; ++j) Prow[j] = g_P[lane * NL + j];
    const float2 g0 = g_g0[lane];
    const float2 g1 = g_g1[lane];

    float wr = 0.0f, wi = 0.0f;

    out[lane]           = 0.0f;      // U[0]
    out[NF * NL + lane] = 0.0f;      // V[0]

    float tax1 = TAx[0], tay1 = TAy[0];

    for (int k = 0; k < NF - 1; ++k) {
        const float tax0 = tax1, tay0 = tay1;
        tax1 = TAx[k + 1];
        tay1 = TAy[k + 1];

        // forcing term: tau_k*g0 + tau_{k+1}*g1 (complex)
        float fr = tax0 * g0.x - tay0 * g0.y + tax1 * g1.x - tay1 * g1.y;
        float fi = tax0 * g0.y + tay0 * g0.x + tax1 * g1.y + tay1 * g1.x;

        // dense complex matvec: 4 accumulator pairs (chain depth 16 FMAs)
        float ar0 = fr,  ai0 = fi;
        float ar1 = 0.f, ai1 = 0.f;
        float ar2 = 0.f, ai2 = 0.f;
        float ar3 = 0.f, ai3 = 0.f;

        #pragma unroll
        for (int j = 0; j < NL; j += 4) {
            float br0 = __shfl_sync(FULL, wr, j + 0);
            float bi0 = __shfl_sync(FULL, wi, j + 0);
            float br1 = __shfl_sync(FULL, wr, j + 1);
            float bi1 = __shfl_sync(FULL, wi, j + 1);
            float br2 = __shfl_sync(FULL, wr, j + 2);
            float bi2 = __shfl_sync(FULL, wi, j + 2);
            float br3 = __shfl_sync(FULL, wr, j + 3);
            float bi3 = __shfl_sync(FULL, wi, j + 3);

            ar0 = fmaf(Prow[j+0].x, br0, ar0); ar0 = fmaf(-Prow[j+0].y, bi0, ar0);
            ai0 = fmaf(Prow[j+0].x, bi0, ai0); ai0 = fmaf( Prow[j+0].y, br0, ai0);
            ar1 = fmaf(Prow[j+1].x, br1, ar1); ar1 = fmaf(-Prow[j+1].y, bi1, ar1);
            ai1 = fmaf(Prow[j+1].x, bi1, ai1); ai1 = fmaf( Prow[j+1].y, br1, ai1);
            ar2 = fmaf(Prow[j+2].x, br2, ar2); ar2 = fmaf(-Prow[j+2].y, bi2, ar2);
            ai2 = fmaf(Prow[j+2].x, bi2, ai2); ai2 = fmaf( Prow[j+2].y, br2, ai2);
            ar3 = fmaf(Prow[j+3].x, br3, ar3); ar3 = fmaf(-Prow[j+3].y, bi3, ar3);
            ai3 = fmaf(Prow[j+3].x, bi3, ai3); ai3 = fmaf( Prow[j+3].y, br3, ai3);
        }

        wr = (ar0 + ar1) + (ar2 + ar3);
        wi = (ai0 + ai1) + (ai2 + ai3);

        out[(k + 1) * NL + lane]           = wr;   // U[k+1]
        out[NF * NL + (k + 1) * NL + lane] = wi;   // V[k+1]
    }
}

extern "C" void kernel_launch(void* const* d_in, const int* in_sizes, int n_in,
                              void* d_out, int out_size)
{
    const float* pk  = (const float*)d_in[0];
    const float* TAx = (const float*)d_in[1];
    const float* TAy = (const float*)d_in[2];
    const float* fc  = (const float*)d_in[3];
    float* out = (float*)d_out;

    setup_kernel<<<1, 1024>>>(pk, fc);
    run_kernel<<<1, 32>>>(TAx, TAy, out);
}